// round 4
// baseline (speedup 1.0000x reference)
#include <cuda_runtime.h>
#include <cstdint>

// ---------------- problem constants ----------------
#define NUM_CODES   1024
#define CODE_DIM    64
#define N_TOKENS    131072
#define DECAY       0.99f
#define OMD         0.01f      /* 1 - DECAY */
#define EPS_F       1e-5f

// ---------------- output layout (flattened tuple, f32) ----------------
// quantized_st [N,D] | indices [N] | loss [1] | new_codebook [K,D] |
// new_cluster_size [K] | new_ema_w [K,D]
#define Q_OFF    0
#define IDX_OFF  (N_TOKENS * CODE_DIM)                 // 8388608
#define LOSS_OFF (IDX_OFF + N_TOKENS)                  // 8519680
#define CB_OFF   (LOSS_OFF + 1)                        // 8519681
#define CS_OFF   (CB_OFF + NUM_CODES * CODE_DIM)       // 8585217
#define EMA_OFF  (CS_OFF + NUM_CODES)                  // 8586241

// ---------------- scratch (no cudaMalloc allowed) ----------------
__device__ float g_counts[NUM_CODES];
__device__ float g_dw[NUM_CODES * CODE_DIM];
__device__ float g_loss;
__device__ float g_n;

// ---------------- packed f32x2 helpers (sm_103a) ----------------
__device__ __forceinline__ unsigned long long ffma2(unsigned long long a,
                                                    unsigned long long b,
                                                    unsigned long long c) {
    unsigned long long d;
    asm("fma.rn.f32x2 %0, %1, %2, %3;" : "=l"(d) : "l"(a), "l"(b), "l"(c));
    return d;
}
__device__ __forceinline__ unsigned long long fadd2(unsigned long long a,
                                                    unsigned long long b) {
    unsigned long long d;
    asm("add.rn.f32x2 %0, %1, %2;" : "=l"(d) : "l"(a), "l"(b));
    return d;
}
__device__ __forceinline__ void unpack2(unsigned long long v, float& lo, float& hi) {
    asm("mov.b64 {%0, %1}, %2;" : "=f"(lo), "=f"(hi) : "l"(v));
}
__device__ __forceinline__ void ldg_v2u64(unsigned long long& a, unsigned long long& b,
                                          const void* p) {
    asm volatile("ld.global.v2.u64 {%0, %1}, [%2];" : "=l"(a), "=l"(b) : "l"(p));
}
__device__ __forceinline__ void lds_v2u64(unsigned long long& a, unsigned long long& b,
                                          unsigned p) {
    asm volatile("ld.shared.v2.u64 {%0, %1}, [%2];" : "=l"(a), "=l"(b) : "r"(p));
}

// ---------------- kernel 0: zero scratch ----------------
__global__ void vq_zero() {
    int i = blockIdx.x * blockDim.x + threadIdx.x;
    if (i < NUM_CODES * CODE_DIM) g_dw[i] = 0.f;
    if (i < NUM_CODES)            g_counts[i] = 0.f;
    if (i == NUM_CODES * CODE_DIM) { g_loss = 0.f; g_n = 0.f; }
}

// ---------------- kernel 1: fused argmin + quantize + stats ----------------
#define TPB   256
#define CHUNK 128   // codes per SMEM tile: 128 * 64 * 4B = 32 KB

__global__ __launch_bounds__(TPB)
void vq_main(const float* __restrict__ z,
             const float* __restrict__ codebook,
             float* __restrict__ out) {
    __shared__ float s_code[CHUNK * CODE_DIM];
    __shared__ float s_c2[CHUNK];
    __shared__ float s_red[TPB / 32];

    const int tid   = threadIdx.x;
    const int token = blockIdx.x * TPB + tid;   // grid sized exactly: no guard

    // z row resident in 32 packed b64 regs: zp[j] = {z[2j], z[2j+1]}
    unsigned long long zp[CODE_DIM / 2];
    const float* zr = z + (size_t)token * CODE_DIM;
    #pragma unroll
    for (int i = 0; i < 16; i++)
        ldg_v2u64(zp[2 * i], zp[2 * i + 1], (const void*)(zr + 4 * i));

    float best = 3.4e38f;
    int   bidx = 0;

    const unsigned scode_addr = (unsigned)__cvta_generic_to_shared(s_code);

    for (int chunk = 0; chunk < NUM_CODES / CHUNK; chunk++) {
        __syncthreads();
        // cooperative stage: 128 codes (8192 floats) -> SMEM
        {
            const float4* src = (const float4*)(codebook + (size_t)chunk * CHUNK * CODE_DIM);
            float4* dst = (float4*)s_code;
            #pragma unroll
            for (int i = 0; i < (CHUNK * CODE_DIM / 4) / TPB; i++)   // 8 iters
                dst[tid + i * TPB] = src[tid + i * TPB];
        }
        __syncthreads();
        // per-code squared norms for this chunk
        if (tid < CHUNK) {
            const float* cr = s_code + tid * CODE_DIM;
            float s = 0.f;
            #pragma unroll
            for (int d = 0; d < CODE_DIM; d++) s += cr[d] * cr[d];
            s_c2[tid] = s;
        }
        __syncthreads();

        for (int c = 0; c < CHUNK; c++) {
            const unsigned caddr = scode_addr + c * (CODE_DIM * 4);
            unsigned long long a0 = 0ull, a1 = 0ull, a2 = 0ull, a3 = 0ull;
            #pragma unroll
            for (int i = 0; i < 8; i++) {
                unsigned long long p0, p1, p2, p3;
                lds_v2u64(p0, p1, caddr + i * 32);        // elems 8i..8i+3 (broadcast)
                lds_v2u64(p2, p3, caddr + i * 32 + 16);   // elems 8i+4..8i+7
                a0 = ffma2(zp[4 * i + 0], p0, a0);
                a1 = ffma2(zp[4 * i + 1], p1, a1);
                a2 = ffma2(zp[4 * i + 2], p2, a2);
                a3 = ffma2(zp[4 * i + 3], p3, a3);
            }
            a0 = fadd2(a0, a1);
            a2 = fadd2(a2, a3);
            a0 = fadd2(a0, a2);
            float lo, hi;
            unpack2(a0, lo, hi);
            const float dot   = lo + hi;
            const float score = s_c2[c] - 2.f * dot;   // z*z constant: drop for argmin
            if (score < best) { best = score; bidx = chunk * CHUNK + c; }  // strict <: first min, matches jnp.argmin
        }
    }

    // ---- epilogue: quantized_st, indices, loss, counts, dw ----
    const float4* q   = (const float4*)(codebook + (size_t)bidx * CODE_DIM);
    float4* qout      = (float4*)(out + Q_OFF + (size_t)token * CODE_DIM);
    float loss = 0.f;
    #pragma unroll
    for (int i = 0; i < 16; i++) {
        float4 qv = q[i];
        float z0, z1, z2, z3;
        unpack2(zp[2 * i],     z0, z1);
        unpack2(zp[2 * i + 1], z2, z3);
        float d0 = z0 - qv.x, d1 = z1 - qv.y, d2 = z2 - qv.z, d3 = z3 - qv.w;
        loss += d0 * d0 + d1 * d1 + d2 * d2 + d3 * d3;
        float4 o;                       // straight-through: z + (q - z), as reference computes
        o.x = z0 + (qv.x - z0);
        o.y = z1 + (qv.y - z1);
        o.z = z2 + (qv.z - z2);
        o.w = z3 + (qv.w - z3);
        qout[i] = o;
    }
    out[IDX_OFF + token] = (float)bidx;

    atomicAdd(&g_counts[bidx], 1.0f);
    float* dwr = g_dw + (size_t)bidx * CODE_DIM;
    #pragma unroll
    for (int i = 0; i < 32; i++) {
        float lo, hi;
        unpack2(zp[i], lo, hi);
        atomicAdd(&dwr[2 * i],     lo);
        atomicAdd(&dwr[2 * i + 1], hi);
    }

    // block-reduce loss, one atomic per block
    #pragma unroll
    for (int o = 16; o; o >>= 1) loss += __shfl_xor_sync(0xffffffffu, loss, o);
    if ((tid & 31) == 0) s_red[tid >> 5] = loss;
    __syncthreads();
    if (tid == 0) {
        float s = 0.f;
        #pragma unroll
        for (int w = 0; w < TPB / 32; w++) s += s_red[w];
        atomicAdd(&g_loss, s);
    }
}

// ---------------- kernel 2: new_cluster_size, n, loss scalar ----------------
__global__ void vq_stats(const float* __restrict__ cluster_size,
                         float* __restrict__ out) {
    __shared__ float s[NUM_CODES];
    const int k = threadIdx.x;
    const float ncs = DECAY * cluster_size[k] + OMD * g_counts[k];
    out[CS_OFF + k] = ncs;
    s[k] = ncs;
    __syncthreads();
    for (int o = NUM_CODES / 2; o > 0; o >>= 1) {
        if (k < o) s[k] += s[k + o];
        __syncthreads();
    }
    if (k == 0) {
        g_n = s[0];
        out[LOSS_OFF] = g_loss / (float)(N_TOKENS * CODE_DIM);
    }
}

// ---------------- kernel 3: new_ema_w + new_codebook ----------------
__global__ void vq_finalize(const float* __restrict__ cluster_size,
                            const float* __restrict__ ema_w,
                            float* __restrict__ out) {
    const int i = blockIdx.x * blockDim.x + threadIdx.x;   // 0..65535
    const int k = i >> 6;
    const float n     = g_n;
    const float ncs   = DECAY * cluster_size[k] + OMD * g_counts[k];
    const float denom = (ncs + EPS_F) / (n + (float)NUM_CODES * EPS_F) * n;
    const float nw    = DECAY * ema_w[i] + OMD * g_dw[i];
    out[EMA_OFF + i] = nw;
    out[CB_OFF + i]  = nw / denom;
}

// ---------------- launch ----------------
extern "C" void kernel_launch(void* const* d_in, const int* in_sizes, int n_in,
                              void* d_out, int out_size) {
    const float* z            = (const float*)d_in[0];
    const float* codebook     = (const float*)d_in[1];
    const float* cluster_size = (const float*)d_in[2];
    const float* ema_w        = (const float*)d_in[3];
    float* out = (float*)d_out;

    vq_zero<<<(NUM_CODES * CODE_DIM + 256) / 256 + 1, 256>>>();
    vq_main<<<N_TOKENS / TPB, TPB>>>(z, codebook, out);
    vq_stats<<<1, NUM_CODES>>>(cluster_size, out);
    vq_finalize<<<NUM_CODES * CODE_DIM / 256, 256>>>(cluster_size, ema_w, out);
}

// round 5
// speedup vs baseline: 1.0027x; 1.0027x over previous
#include <cuda_runtime.h>
#include <cstdint>

// ---------------- problem constants ----------------
#define NUM_CODES   1024
#define CODE_DIM    64
#define N_TOKENS    131072
#define DECAY       0.99f
#define OMD         0.01f      /* 1 - DECAY */
#define EPS_F       1e-5f

// ---------------- output layout (flattened tuple, f32) ----------------
// quantized_st [N,D] | indices [N] | loss [1] | new_codebook [K,D] |
// new_cluster_size [K] | new_ema_w [K,D]
#define Q_OFF    0
#define IDX_OFF  (N_TOKENS * CODE_DIM)                 // 8388608
#define LOSS_OFF (IDX_OFF + N_TOKENS)                  // 8519680
#define CB_OFF   (LOSS_OFF + 1)                        // 8519681
#define CS_OFF   (CB_OFF + NUM_CODES * CODE_DIM)       // 8585217
#define EMA_OFF  (CS_OFF + NUM_CODES)                  // 8586241

// ---------------- scratch (no cudaMalloc allowed) ----------------
__device__ float g_counts[NUM_CODES];
__device__ float g_dw[NUM_CODES * CODE_DIM];
__device__ float g_loss;
__device__ float g_n;

// ---------------- packed f32x2 helpers (sm_103a) ----------------
__device__ __forceinline__ unsigned long long ffma2(unsigned long long a,
                                                    unsigned long long b,
                                                    unsigned long long c) {
    unsigned long long d;
    asm("fma.rn.f32x2 %0, %1, %2, %3;" : "=l"(d) : "l"(a), "l"(b), "l"(c));
    return d;
}
__device__ __forceinline__ unsigned long long fadd2(unsigned long long a,
                                                    unsigned long long b) {
    unsigned long long d;
    asm("add.rn.f32x2 %0, %1, %2;" : "=l"(d) : "l"(a), "l"(b));
    return d;
}
__device__ __forceinline__ void unpack2(unsigned long long v, float& lo, float& hi) {
    asm("mov.b64 {%0, %1}, %2;" : "=f"(lo), "=f"(hi) : "l"(v));
}
__device__ __forceinline__ void ldg_v2u64(unsigned long long& a, unsigned long long& b,
                                          const void* p) {
    asm volatile("ld.global.v2.u64 {%0, %1}, [%2];" : "=l"(a), "=l"(b) : "l"(p));
}
__device__ __forceinline__ void lds_v2u64(unsigned long long& a, unsigned long long& b,
                                          unsigned p) {
    asm volatile("ld.shared.v2.u64 {%0, %1}, [%2];" : "=l"(a), "=l"(b) : "r"(p));
}

// ---------------- kernel 0: zero scratch ----------------
__global__ void vq_zero() {
    int i = blockIdx.x * blockDim.x + threadIdx.x;
    if (i < NUM_CODES * CODE_DIM) g_dw[i] = 0.f;
    if (i < NUM_CODES)            g_counts[i] = 0.f;
    if (i == NUM_CODES * CODE_DIM) { g_loss = 0.f; g_n = 0.f; }
}

// ---------------- kernel 1: fused argmin + quantize + stats ----------------
#define TPB   256
#define CHUNK 128   // codes per SMEM tile: 128 * 64 * 4B = 32 KB

__global__ __launch_bounds__(TPB)
void vq_main(const float* __restrict__ z,
             const float* __restrict__ codebook,
             float* __restrict__ out) {
    __shared__ float s_code[CHUNK * CODE_DIM];
    __shared__ float s_c2[CHUNK];
    __shared__ float s_red[TPB / 32];

    const int tid   = threadIdx.x;
    const int token = blockIdx.x * TPB + tid;   // grid sized exactly: no guard

    // z row resident in 32 packed b64 regs: zp[j] = {z[2j], z[2j+1]}
    unsigned long long zp[CODE_DIM / 2];
    const float* zr = z + (size_t)token * CODE_DIM;
    #pragma unroll
    for (int i = 0; i < 16; i++)
        ldg_v2u64(zp[2 * i], zp[2 * i + 1], (const void*)(zr + 4 * i));

    float best = 3.4e38f;
    int   bidx = 0;

    const unsigned scode_addr = (unsigned)__cvta_generic_to_shared(s_code);

    for (int chunk = 0; chunk < NUM_CODES / CHUNK; chunk++) {
        __syncthreads();
        // cooperative stage: 128 codes (8192 floats) -> SMEM
        {
            const float4* src = (const float4*)(codebook + (size_t)chunk * CHUNK * CODE_DIM);
            float4* dst = (float4*)s_code;
            #pragma unroll
            for (int i = 0; i < (CHUNK * CODE_DIM / 4) / TPB; i++)   // 8 iters
                dst[tid + i * TPB] = src[tid + i * TPB];
        }
        __syncthreads();
        // per-code squared norms for this chunk
        if (tid < CHUNK) {
            const float* cr = s_code + tid * CODE_DIM;
            float s = 0.f;
            #pragma unroll
            for (int d = 0; d < CODE_DIM; d++) s += cr[d] * cr[d];
            s_c2[tid] = s;
        }
        __syncthreads();

        for (int c = 0; c < CHUNK; c++) {
            const unsigned caddr = scode_addr + c * (CODE_DIM * 4);
            unsigned long long a0 = 0ull, a1 = 0ull, a2 = 0ull, a3 = 0ull;
            #pragma unroll
            for (int i = 0; i < 8; i++) {
                unsigned long long p0, p1, p2, p3;
                lds_v2u64(p0, p1, caddr + i * 32);        // elems 8i..8i+3 (broadcast)
                lds_v2u64(p2, p3, caddr + i * 32 + 16);   // elems 8i+4..8i+7
                a0 = ffma2(zp[4 * i + 0], p0, a0);
                a1 = ffma2(zp[4 * i + 1], p1, a1);
                a2 = ffma2(zp[4 * i + 2], p2, a2);
                a3 = ffma2(zp[4 * i + 3], p3, a3);
            }
            a0 = fadd2(a0, a1);
            a2 = fadd2(a2, a3);
            a0 = fadd2(a0, a2);
            float lo, hi;
            unpack2(a0, lo, hi);
            const float dot   = lo + hi;
            const float score = s_c2[c] - 2.f * dot;   // z*z constant: drop for argmin
            if (score < best) { best = score; bidx = chunk * CHUNK + c; }  // strict <: first min, matches jnp.argmin
        }
    }

    // ---- epilogue: quantized_st, indices, loss, counts, dw ----
    const float4* q   = (const float4*)(codebook + (size_t)bidx * CODE_DIM);
    float4* qout      = (float4*)(out + Q_OFF + (size_t)token * CODE_DIM);
    float loss = 0.f;
    #pragma unroll
    for (int i = 0; i < 16; i++) {
        float4 qv = q[i];
        float z0, z1, z2, z3;
        unpack2(zp[2 * i],     z0, z1);
        unpack2(zp[2 * i + 1], z2, z3);
        float d0 = z0 - qv.x, d1 = z1 - qv.y, d2 = z2 - qv.z, d3 = z3 - qv.w;
        loss += d0 * d0 + d1 * d1 + d2 * d2 + d3 * d3;
        float4 o;                       // straight-through: z + (q - z), as reference computes
        o.x = z0 + (qv.x - z0);
        o.y = z1 + (qv.y - z1);
        o.z = z2 + (qv.z - z2);
        o.w = z3 + (qv.w - z3);
        qout[i] = o;
    }
    out[IDX_OFF + token] = (float)bidx;

    atomicAdd(&g_counts[bidx], 1.0f);
    float* dwr = g_dw + (size_t)bidx * CODE_DIM;
    #pragma unroll
    for (int i = 0; i < 32; i++) {
        float lo, hi;
        unpack2(zp[i], lo, hi);
        atomicAdd(&dwr[2 * i],     lo);
        atomicAdd(&dwr[2 * i + 1], hi);
    }

    // block-reduce loss, one atomic per block
    #pragma unroll
    for (int o = 16; o; o >>= 1) loss += __shfl_xor_sync(0xffffffffu, loss, o);
    if ((tid & 31) == 0) s_red[tid >> 5] = loss;
    __syncthreads();
    if (tid == 0) {
        float s = 0.f;
        #pragma unroll
        for (int w = 0; w < TPB / 32; w++) s += s_red[w];
        atomicAdd(&g_loss, s);
    }
}

// ---------------- kernel 2: new_cluster_size, n, loss scalar ----------------
__global__ void vq_stats(const float* __restrict__ cluster_size,
                         float* __restrict__ out) {
    __shared__ float s[NUM_CODES];
    const int k = threadIdx.x;
    const float ncs = DECAY * cluster_size[k] + OMD * g_counts[k];
    out[CS_OFF + k] = ncs;
    s[k] = ncs;
    __syncthreads();
    for (int o = NUM_CODES / 2; o > 0; o >>= 1) {
        if (k < o) s[k] += s[k + o];
        __syncthreads();
    }
    if (k == 0) {
        g_n = s[0];
        out[LOSS_OFF] = g_loss / (float)(N_TOKENS * CODE_DIM);
    }
}

// ---------------- kernel 3: new_ema_w + new_codebook ----------------
__global__ void vq_finalize(const float* __restrict__ cluster_size,
                            const float* __restrict__ ema_w,
                            float* __restrict__ out) {
    const int i = blockIdx.x * blockDim.x + threadIdx.x;   // 0..65535
    const int k = i >> 6;
    const float n     = g_n;
    const float ncs   = DECAY * cluster_size[k] + OMD * g_counts[k];
    const float denom = (ncs + EPS_F) / (n + (float)NUM_CODES * EPS_F) * n;
    const float nw    = DECAY * ema_w[i] + OMD * g_dw[i];
    out[EMA_OFF + i] = nw;
    out[CB_OFF + i]  = nw / denom;
}

// ---------------- launch ----------------
extern "C" void kernel_launch(void* const* d_in, const int* in_sizes, int n_in,
                              void* d_out, int out_size) {
    const float* z            = (const float*)d_in[0];
    const float* codebook     = (const float*)d_in[1];
    const float* cluster_size = (const float*)d_in[2];
    const float* ema_w        = (const float*)d_in[3];
    float* out = (float*)d_out;

    vq_zero<<<(NUM_CODES * CODE_DIM + 256) / 256 + 1, 256>>>();
    vq_main<<<N_TOKENS / TPB, TPB>>>(z, codebook, out);
    vq_stats<<<1, NUM_CODES>>>(cluster_size, out);
    vq_finalize<<<NUM_CODES * CODE_DIM / 256, 256>>>(cluster_size, ema_w, out);
}

// round 12
// speedup vs baseline: 2.1089x; 2.1032x over previous
#include <cuda_runtime.h>
#include <cuda_bf16.h>
#include <cstdint>

// ---------------- problem constants ----------------
#define NUM_CODES   1024
#define CODE_DIM    64
#define N_TOKENS    131072
#define DECAY       0.99f
#define OMD         0.01f
#define EPS_F       1e-5f

#define N_MTILES    (N_TOKENS / 16)    // 8192 (16 tokens per warp-tile)
#define N_NTILES    (NUM_CODES / 8)    // 128  (8 codes per mma N-tile)

// ---------------- output layout (flattened tuple, f32) ----------------
#define Q_OFF    0
#define IDX_OFF  (N_TOKENS * CODE_DIM)
#define LOSS_OFF (IDX_OFF + N_TOKENS)
#define CB_OFF   (LOSS_OFF + 1)
#define CS_OFF   (CB_OFF + NUM_CODES * CODE_DIM)
#define EMA_OFF  (CS_OFF + NUM_CODES)

// ---------------- scratch (small only — no huge statics) ----------------
__device__ float g_counts[NUM_CODES];
__device__ float g_dw[NUM_CODES * CODE_DIM];
__device__ float g_loss;
__device__ float g_n;
__device__ float g_h[NUM_CODES];   // ||c||^2

// B fragments: [ntile][chunk i=0..5][lane][4 x u32]  (u32 j = Lb*8 + kstep*2 + {0,1})
// 128 * 6 * 32 * 4 * 4 B = 393 KB — L2-resident.
__device__ unsigned g_Bfrag[(size_t)N_NTILES * 6 * 32 * 4];

// ---------------- helpers ----------------
__device__ __forceinline__ void split3(float x, unsigned short& a, unsigned short& b,
                                       unsigned short& c) {
    __nv_bfloat16 ha = __float2bfloat16_rn(x);
    float r1 = x - __bfloat162float(ha);
    __nv_bfloat16 hb = __float2bfloat16_rn(r1);
    float r2 = r1 - __bfloat162float(hb);
    __nv_bfloat16 hc = __float2bfloat16_rn(r2);
    a = __bfloat16_as_ushort(ha);
    b = __bfloat16_as_ushort(hb);
    c = __bfloat16_as_ushort(hc);
}
__device__ __forceinline__ unsigned pck(unsigned short lo, unsigned short hi) {
    return (unsigned)lo | ((unsigned)hi << 16);
}
__device__ __forceinline__ void mma16816(float& c0, float& c1, float& c2, float& c3,
                                         unsigned a0, unsigned a1, unsigned a2, unsigned a3,
                                         unsigned b0, unsigned b1) {
    asm volatile(
        "mma.sync.aligned.m16n8k16.row.col.f32.bf16.bf16.f32 "
        "{%0,%1,%2,%3}, {%4,%5,%6,%7}, {%8,%9}, {%0,%1,%2,%3};"
        : "+f"(c0), "+f"(c1), "+f"(c2), "+f"(c3)
        : "r"(a0), "r"(a1), "r"(a2), "r"(a3), "r"(b0), "r"(b1));
}
__device__ __forceinline__ void red_v4(float* p, float4 v) {
    asm volatile("red.global.add.v4.f32 [%0], {%1, %2, %3, %4};"
                 :: "l"(p), "f"(v.x), "f"(v.y), "f"(v.z), "f"(v.w) : "memory");
}

// ---------------- kernel 0: zero scratch ----------------
__global__ void vq_zero() {
    int i = blockIdx.x * blockDim.x + threadIdx.x;
    if (i < NUM_CODES * CODE_DIM) g_dw[i] = 0.f;
    if (i < NUM_CODES)            g_counts[i] = 0.f;
    if (i == NUM_CODES * CODE_DIM) { g_loss = 0.f; g_n = 0.f; }
}

// ---------------- kernel 1: codebook -> B fragments + norms ----------------
// B frag (col-major [N,K]), lane l: code n = ntile*8 + l/4, c0=2*(l%4):
//   b0 = B[n][k16+c0,+1]   b1 = B[n][k16+c0+8,+9]
__global__ __launch_bounds__(256)
void vq_prep_cb(const float* __restrict__ codebook) {
    int gid   = blockIdx.x * 256 + threadIdx.x;     // 0 .. N_NTILES*32-1
    int ntile = gid >> 5, lane = gid & 31;
    int n  = ntile * 8 + (lane >> 2);
    int c0 = (lane & 3) * 2;
    const float* cr = codebook + (size_t)n * CODE_DIM;

    unsigned ob[24];
    #pragma unroll
    for (int k = 0; k < 4; k++) {
        float2 f0 = *(const float2*)(cr + k * 16 + c0);
        float2 f1 = *(const float2*)(cr + k * 16 + c0 + 8);
        float f[4] = {f0.x, f0.y, f1.x, f1.y};
        unsigned short L0[4], L1[4], L2[4];
        #pragma unroll
        for (int i = 0; i < 4; i++) split3(f[i], L0[i], L1[i], L2[i]);
        #pragma unroll
        for (int j = 0; j < 2; j++) {
            ob[0 * 8 + k * 2 + j] = pck(L0[2 * j], L0[2 * j + 1]);
            ob[1 * 8 + k * 2 + j] = pck(L1[2 * j], L1[2 * j + 1]);
            ob[2 * 8 + k * 2 + j] = pck(L2[2 * j], L2[2 * j + 1]);
        }
    }
    #pragma unroll
    for (int i = 0; i < 6; i++) {
        uint4 v = make_uint4(ob[4 * i], ob[4 * i + 1], ob[4 * i + 2], ob[4 * i + 3]);
        *(uint4*)(g_Bfrag + (((size_t)ntile * 6 + i) * 32 + lane) * 4) = v;
    }
    if ((lane & 3) == 0) {
        float s = 0.f;
        #pragma unroll
        for (int d = 0; d < CODE_DIM; d++) s += cr[d] * cr[d];
        g_h[n] = s;
    }
}

// ---------------- kernel 2: HMMA distance GEMM + fused argmin + epilogue ----------------
__global__ __launch_bounds__(256, 2)
void vq_main(const float* __restrict__ z,
             const float* __restrict__ codebook,
             float* __restrict__ out) {
    const unsigned FULL = 0xffffffffu;
    const int lane = threadIdx.x & 31;
    const int wid  = threadIdx.x >> 5;
    const int m    = blockIdx.x * 8 + wid;          // mtile: tokens m*16 .. m*16+15
    const int c0i  = (lane & 3) * 2;

    // Build A fragments in-register from z (m16n8k16 A frag, row-major):
    // lane l: group g=l/4, c0=2*(l%4):
    //   a0 = A[g][k16+c0,+1]   a1 = A[g+8][k16+c0,+1]
    //   a2 = A[g][k16+c0+8,+9] a3 = A[g+8][k16+c0+8,+9]
    // Af chunk index = La*4 + kstep, (x,y,z,w) = (a0,a1,a2,a3).
    uint4 Af[12];
    {
        const int g = lane >> 2;
        const float* z0 = z + (size_t)(m * 16 + g) * CODE_DIM;
        const float* z1 = z0 + 8 * CODE_DIM;
        #pragma unroll
        for (int k = 0; k < 4; k++) {
            float2 f0 = *(const float2*)(z0 + k * 16 + c0i);
            float2 f1 = *(const float2*)(z1 + k * 16 + c0i);
            float2 f2 = *(const float2*)(z0 + k * 16 + c0i + 8);
            float2 f3 = *(const float2*)(z1 + k * 16 + c0i + 8);
            float f[8] = {f0.x, f0.y, f1.x, f1.y, f2.x, f2.y, f3.x, f3.y};
            unsigned short L0[8], L1[8], L2[8];
            #pragma unroll
            for (int i = 0; i < 8; i++) split3(f[i], L0[i], L1[i], L2[i]);
            Af[0 * 4 + k] = make_uint4(pck(L0[0], L0[1]), pck(L0[2], L0[3]),
                                       pck(L0[4], L0[5]), pck(L0[6], L0[7]));
            Af[1 * 4 + k] = make_uint4(pck(L1[0], L1[1]), pck(L1[2], L1[3]),
                                       pck(L1[4], L1[5]), pck(L1[6], L1[7]));
            Af[2 * 4 + k] = make_uint4(pck(L2[0], L2[1]), pck(L2[2], L2[3]),
                                       pck(L2[4], L2[5]), pck(L2[6], L2[7]));
        }
    }

    float best0 = 3.4e38f, best1 = 3.4e38f;
    int   bi0 = 0, bi1 = 0;

    // limb-product pairs, smallest magnitude first: (0,2)(2,0)(1,1)(0,1)(1,0)(0,0)
    const int PLa[6] = {0, 2, 1, 0, 1, 0};
    const int PLb[6] = {2, 0, 1, 1, 0, 0};

    for (int n = 0; n < N_NTILES; n++) {
        unsigned Bk[24];
        #pragma unroll
        for (int i = 0; i < 6; i++) {
            uint4 t = *(const uint4*)(g_Bfrag + (((size_t)n * 6 + i) * 32 + lane) * 4);
            Bk[4 * i] = t.x; Bk[4 * i + 1] = t.y; Bk[4 * i + 2] = t.z; Bk[4 * i + 3] = t.w;
        }
        float2 h2 = *(const float2*)(g_h + n * 8 + c0i);

        float c0 = 0.f, c1 = 0.f, c2 = 0.f, c3 = 0.f;
        #pragma unroll
        for (int pi = 0; pi < 6; pi++) {
            const int La = PLa[pi], Lb = PLb[pi];
            #pragma unroll
            for (int k = 0; k < 4; k++) {
                uint4 a = Af[La * 4 + k];
                mma16816(c0, c1, c2, c3, a.x, a.y, a.z, a.w,
                         Bk[Lb * 8 + k * 2], Bk[Lb * 8 + k * 2 + 1]);
            }
        }
        // score = ||c||^2 - 2*dot  (||z||^2 constant per token: irrelevant for argmin)
        float s0 = fmaf(-2.f, c0, h2.x);
        float s1 = fmaf(-2.f, c1, h2.y);
        float s2 = fmaf(-2.f, c2, h2.x);
        float s3 = fmaf(-2.f, c3, h2.y);
        const int base = n * 8 + c0i;
        if (s0 < best0) { best0 = s0; bi0 = base; }
        if (s1 < best0) { best0 = s1; bi0 = base + 1; }
        if (s2 < best1) { best1 = s2; bi1 = base; }
        if (s3 < best1) { best1 = s3; bi1 = base + 1; }
    }

    // reduce across the 4 lanes of each row-quad (tie -> lower index = first min)
    #pragma unroll
    for (int off = 1; off < 4; off <<= 1) {
        float ob0 = __shfl_xor_sync(FULL, best0, off);
        int   oi0 = __shfl_xor_sync(FULL, bi0, off);
        if (ob0 < best0 || (ob0 == best0 && oi0 < bi0)) { best0 = ob0; bi0 = oi0; }
        float ob1 = __shfl_xor_sync(FULL, best1, off);
        int   oi1 = __shfl_xor_sync(FULL, bi1, off);
        if (ob1 < best1 || (ob1 == best1 && oi1 < bi1)) { best1 = ob1; bi1 = oi1; }
    }

    // redistribute: 2 lanes per token (each handles 32 of 64 dims)
    const int t    = lane >> 1;
    const int half = lane & 1;
    const int src  = 4 * (t & 7);
    const int v0 = __shfl_sync(FULL, bi0, src);
    const int v1 = __shfl_sync(FULL, bi1, src);
    const int besti = (t < 8) ? v0 : v1;
    const int token = m * 16 + t;

    const float4* zr = (const float4*)(z + (size_t)token * CODE_DIM + half * 32);
    const float4* qr = (const float4*)(codebook + (size_t)besti * CODE_DIM + half * 32);
    float4* qo = (float4*)(out + Q_OFF + (size_t)token * CODE_DIM + half * 32);
    float*  dwr = g_dw + (size_t)besti * CODE_DIM + half * 32;

    float loss = 0.f;
    #pragma unroll
    for (int i = 0; i < 8; i++) {
        float4 zv = zr[i];
        float4 qv = qr[i];
        float d0 = zv.x - qv.x, d1 = zv.y - qv.y, d2 = zv.z - qv.z, d3 = zv.w - qv.w;
        loss += d0 * d0 + d1 * d1 + d2 * d2 + d3 * d3;
        float4 o;                     // straight-through: z + (q - z), as reference
        o.x = zv.x + (qv.x - zv.x);
        o.y = zv.y + (qv.y - zv.y);
        o.z = zv.z + (qv.z - zv.z);
        o.w = zv.w + (qv.w - zv.w);
        qo[i] = o;
        red_v4(dwr + 4 * i, zv);
    }
    if (!half) {
        out[IDX_OFF + token] = (float)besti;
        atomicAdd(&g_counts[besti], 1.0f);
    }
    #pragma unroll
    for (int off = 16; off; off >>= 1) loss += __shfl_xor_sync(FULL, loss, off);
    if (lane == 0) atomicAdd(&g_loss, loss);
}

// ---------------- kernel 3: new_cluster_size, n, loss scalar ----------------
__global__ void vq_stats(const float* __restrict__ cluster_size,
                         float* __restrict__ out) {
    __shared__ float s[NUM_CODES];
    const int k = threadIdx.x;
    const float ncs = DECAY * cluster_size[k] + OMD * g_counts[k];
    out[CS_OFF + k] = ncs;
    s[k] = ncs;
    __syncthreads();
    for (int o = NUM_CODES / 2; o > 0; o >>= 1) {
        if (k < o) s[k] += s[k + o];
        __syncthreads();
    }
    if (k == 0) {
        g_n = s[0];
        out[LOSS_OFF] = g_loss / (float)(N_TOKENS * CODE_DIM);
    }
}

// ---------------- kernel 4: new_ema_w + new_codebook ----------------
__global__ void vq_finalize(const float* __restrict__ cluster_size,
                            const float* __restrict__ ema_w,
                            float* __restrict__ out) {
    const int i = blockIdx.x * blockDim.x + threadIdx.x;
    const int k = i >> 6;
    const float n     = g_n;
    const float ncs   = DECAY * cluster_size[k] + OMD * g_counts[k];
    const float denom = (ncs + EPS_F) / (n + (float)NUM_CODES * EPS_F) * n;
    const float nw    = DECAY * ema_w[i] + OMD * g_dw[i];
    out[EMA_OFF + i] = nw;
    out[CB_OFF + i]  = nw / denom;
}

// ---------------- launch ----------------
extern "C" void kernel_launch(void* const* d_in, const int* in_sizes, int n_in,
                              void* d_out, int out_size) {
    const float* z            = (const float*)d_in[0];
    const float* codebook     = (const float*)d_in[1];
    const float* cluster_size = (const float*)d_in[2];
    const float* ema_w        = (const float*)d_in[3];
    float* out = (float*)d_out;

    vq_zero<<<(NUM_CODES * CODE_DIM + 256) / 256 + 1, 256>>>();
    vq_prep_cb<<<(N_NTILES * 32) / 256, 256>>>(codebook);
    vq_main<<<N_MTILES / 8, 256>>>(z, codebook, out);
    vq_stats<<<1, NUM_CODES>>>(cluster_size, out);
    vq_finalize<<<NUM_CODES * CODE_DIM / 256, 256>>>(cluster_size, ema_w, out);
}

// round 15
// speedup vs baseline: 4.2333x; 2.0073x over previous
#include <cuda_runtime.h>
#include <cuda_fp16.h>
#include <cstdint>

// ---------------- problem constants ----------------
#define NUM_CODES   1024
#define CODE_DIM    64
#define N_TOKENS    131072
#define DECAY       0.99f
#define OMD         0.01f
#define EPS_F       1e-5f

#define N_MTILES    (N_TOKENS / 16)    // 8192 (16 tokens per warp-tile)
#define N_NTILES    (NUM_CODES / 8)    // 128  (8 codes per mma N-tile)

// ---------------- output layout (flattened tuple, f32) ----------------
#define Q_OFF    0
#define IDX_OFF  (N_TOKENS * CODE_DIM)
#define LOSS_OFF (IDX_OFF + N_TOKENS)
#define CB_OFF   (LOSS_OFF + 1)
#define CS_OFF   (CB_OFF + NUM_CODES * CODE_DIM)
#define EMA_OFF  (CS_OFF + NUM_CODES)

// ---------------- scratch (small only) ----------------
__device__ float g_counts[NUM_CODES];
__device__ float g_dw[NUM_CODES * CODE_DIM];
__device__ float g_loss;
__device__ float g_n;
__device__ float g_h[NUM_CODES];   // ||c||^2

// B fragments: [ntile][chunk i=0..3][lane][4 x u32]  (u32 j = Lb*8 + kstep*2 + {0,1})
// 128 * 4 * 32 * 4 * 4 B = 256 KB — L2-resident.
__device__ unsigned g_Bfrag[(size_t)N_NTILES * 4 * 32 * 4];

// ---------------- helpers ----------------
// fp16 2-limb split: x = l0 + l1 + O(2^-24 * |x|)
__device__ __forceinline__ void split2h(float x, unsigned short& a, unsigned short& b) {
    __half h0 = __float2half_rn(x);
    float r1 = x - __half2float(h0);
    __half h1 = __float2half_rn(r1);
    a = __half_as_ushort(h0);
    b = __half_as_ushort(h1);
}
__device__ __forceinline__ unsigned pck(unsigned short lo, unsigned short hi) {
    return (unsigned)lo | ((unsigned)hi << 16);
}
__device__ __forceinline__ void mma16816h(float& c0, float& c1, float& c2, float& c3,
                                          unsigned a0, unsigned a1, unsigned a2, unsigned a3,
                                          unsigned b0, unsigned b1) {
    asm volatile(
        "mma.sync.aligned.m16n8k16.row.col.f32.f16.f16.f32 "
        "{%0,%1,%2,%3}, {%4,%5,%6,%7}, {%8,%9}, {%0,%1,%2,%3};"
        : "+f"(c0), "+f"(c1), "+f"(c2), "+f"(c3)
        : "r"(a0), "r"(a1), "r"(a2), "r"(a3), "r"(b0), "r"(b1));
}
__device__ __forceinline__ void red_v4(float* p, float4 v) {
    asm volatile("red.global.add.v4.f32 [%0], {%1, %2, %3, %4};"
                 :: "l"(p), "f"(v.x), "f"(v.y), "f"(v.z), "f"(v.w) : "memory");
}

// ---------------- kernel 0: zero scratch ----------------
__global__ void vq_zero() {
    int i = blockIdx.x * blockDim.x + threadIdx.x;
    if (i < NUM_CODES * CODE_DIM) g_dw[i] = 0.f;
    if (i < NUM_CODES)            g_counts[i] = 0.f;
    if (i == NUM_CODES * CODE_DIM) { g_loss = 0.f; g_n = 0.f; }
}

// ---------------- kernel 1: codebook -> fp16 2-limb B fragments + norms ----------------
// B frag (col-major [N,K]), lane l: code n = ntile*8 + l/4, c0=2*(l%4):
//   b0 = B[n][k16+c0,+1]   b1 = B[n][k16+c0+8,+9]
__global__ __launch_bounds__(256)
void vq_prep_cb(const float* __restrict__ codebook) {
    int gid   = blockIdx.x * 256 + threadIdx.x;     // 0 .. N_NTILES*32-1
    int ntile = gid >> 5, lane = gid & 31;
    int n  = ntile * 8 + (lane >> 2);
    int c0 = (lane & 3) * 2;
    const float* cr = codebook + (size_t)n * CODE_DIM;

    unsigned ob[16];
    #pragma unroll
    for (int k = 0; k < 4; k++) {
        float2 f0 = *(const float2*)(cr + k * 16 + c0);
        float2 f1 = *(const float2*)(cr + k * 16 + c0 + 8);
        float f[4] = {f0.x, f0.y, f1.x, f1.y};
        unsigned short L0[4], L1[4];
        #pragma unroll
        for (int i = 0; i < 4; i++) split2h(f[i], L0[i], L1[i]);
        #pragma unroll
        for (int j = 0; j < 2; j++) {
            ob[0 * 8 + k * 2 + j] = pck(L0[2 * j], L0[2 * j + 1]);
            ob[1 * 8 + k * 2 + j] = pck(L1[2 * j], L1[2 * j + 1]);
        }
    }
    #pragma unroll
    for (int i = 0; i < 4; i++) {
        uint4 v = make_uint4(ob[4 * i], ob[4 * i + 1], ob[4 * i + 2], ob[4 * i + 3]);
        *(uint4*)(g_Bfrag + (((size_t)ntile * 4 + i) * 32 + lane) * 4) = v;
    }
    if ((lane & 3) == 0) {
        float s = 0.f;
        #pragma unroll
        for (int d = 0; d < CODE_DIM; d++) s += cr[d] * cr[d];
        g_h[n] = s;
    }
}

// ---------------- kernel 2: HMMA distance GEMM + fused argmin + epilogue ----------------
__global__ __launch_bounds__(256, 2)
void vq_main(const float* __restrict__ z,
             const float* __restrict__ codebook,
             float* __restrict__ out) {
    const unsigned FULL = 0xffffffffu;
    const int lane = threadIdx.x & 31;
    const int wid  = threadIdx.x >> 5;
    const int m    = blockIdx.x * 8 + wid;          // mtile: tokens m*16 .. m*16+15
    const int c0i  = (lane & 3) * 2;

    // Build A fragments in-register from z (m16n8k16 A frag, row-major):
    // lane l: group g=l/4, c0=2*(l%4):
    //   a0 = A[g][k16+c0,+1]   a1 = A[g+8][k16+c0,+1]
    //   a2 = A[g][k16+c0+8,+9] a3 = A[g+8][k16+c0+8,+9]
    // Af chunk index = La*4 + kstep, (x,y,z,w) = (a0,a1,a2,a3).
    uint4 Af[8];
    {
        const int g = lane >> 2;
        const float* z0 = z + (size_t)(m * 16 + g) * CODE_DIM;
        const float* z1 = z0 + 8 * CODE_DIM;
        #pragma unroll
        for (int k = 0; k < 4; k++) {
            float2 f0 = *(const float2*)(z0 + k * 16 + c0i);
            float2 f1 = *(const float2*)(z1 + k * 16 + c0i);
            float2 f2 = *(const float2*)(z0 + k * 16 + c0i + 8);
            float2 f3 = *(const float2*)(z1 + k * 16 + c0i + 8);
            float f[8] = {f0.x, f0.y, f1.x, f1.y, f2.x, f2.y, f3.x, f3.y};
            unsigned short L0[8], L1[8];
            #pragma unroll
            for (int i = 0; i < 8; i++) split2h(f[i], L0[i], L1[i]);
            Af[0 * 4 + k] = make_uint4(pck(L0[0], L0[1]), pck(L0[2], L0[3]),
                                       pck(L0[4], L0[5]), pck(L0[6], L0[7]));
            Af[1 * 4 + k] = make_uint4(pck(L1[0], L1[1]), pck(L1[2], L1[3]),
                                       pck(L1[4], L1[5]), pck(L1[6], L1[7]));
        }
    }

    float best0 = 3.4e38f, best1 = 3.4e38f;
    int   bi0 = 0, bi1 = 0;

    // limb-product pairs, smallest magnitude first: (0,1)(1,0)(0,0)
    const int PLa[3] = {0, 1, 0};
    const int PLb[3] = {1, 0, 0};

    for (int n = 0; n < N_NTILES; n++) {
        unsigned Bk[16];
        #pragma unroll
        for (int i = 0; i < 4; i++) {
            uint4 t = *(const uint4*)(g_Bfrag + (((size_t)n * 4 + i) * 32 + lane) * 4);
            Bk[4 * i] = t.x; Bk[4 * i + 1] = t.y; Bk[4 * i + 2] = t.z; Bk[4 * i + 3] = t.w;
        }
        float2 h2 = *(const float2*)(g_h + n * 8 + c0i);

        float c0 = 0.f, c1 = 0.f, c2 = 0.f, c3 = 0.f;
        #pragma unroll
        for (int pi = 0; pi < 3; pi++) {
            const int La = PLa[pi], Lb = PLb[pi];
            #pragma unroll
            for (int k = 0; k < 4; k++) {
                uint4 a = Af[La * 4 + k];
                mma16816h(c0, c1, c2, c3, a.x, a.y, a.z, a.w,
                          Bk[Lb * 8 + k * 2], Bk[Lb * 8 + k * 2 + 1]);
            }
        }
        // score = ||c||^2 - 2*dot  (||z||^2 constant per token: irrelevant for argmin)
        float s0 = fmaf(-2.f, c0, h2.x);
        float s1 = fmaf(-2.f, c1, h2.y);
        float s2 = fmaf(-2.f, c2, h2.x);
        float s3 = fmaf(-2.f, c3, h2.y);
        const int base = n * 8 + c0i;
        if (s0 < best0) { best0 = s0; bi0 = base; }
        if (s1 < best0) { best0 = s1; bi0 = base + 1; }
        if (s2 < best1) { best1 = s2; bi1 = base; }
        if (s3 < best1) { best1 = s3; bi1 = base + 1; }
    }

    // reduce across the 4 lanes of each row-quad (tie -> lower index = first min)
    #pragma unroll
    for (int off = 1; off < 4; off <<= 1) {
        float ob0 = __shfl_xor_sync(FULL, best0, off);
        int   oi0 = __shfl_xor_sync(FULL, bi0, off);
        if (ob0 < best0 || (ob0 == best0 && oi0 < bi0)) { best0 = ob0; bi0 = oi0; }
        float ob1 = __shfl_xor_sync(FULL, best1, off);
        int   oi1 = __shfl_xor_sync(FULL, bi1, off);
        if (ob1 < best1 || (ob1 == best1 && oi1 < bi1)) { best1 = ob1; bi1 = oi1; }
    }

    // redistribute: 2 lanes per token (each handles 32 of 64 dims)
    const int t    = lane >> 1;
    const int half = lane & 1;
    const int src  = 4 * (t & 7);
    const int v0 = __shfl_sync(FULL, bi0, src);
    const int v1 = __shfl_sync(FULL, bi1, src);
    const int besti = (t < 8) ? v0 : v1;
    const int token = m * 16 + t;

    const float4* zr = (const float4*)(z + (size_t)token * CODE_DIM + half * 32);
    const float4* qr = (const float4*)(codebook + (size_t)besti * CODE_DIM + half * 32);
    float4* qo = (float4*)(out + Q_OFF + (size_t)token * CODE_DIM + half * 32);
    float*  dwr = g_dw + (size_t)besti * CODE_DIM + half * 32;

    float loss = 0.f;
    #pragma unroll
    for (int i = 0; i < 8; i++) {
        float4 zv = zr[i];
        float4 qv = qr[i];
        float d0 = zv.x - qv.x, d1 = zv.y - qv.y, d2 = zv.z - qv.z, d3 = zv.w - qv.w;
        loss += d0 * d0 + d1 * d1 + d2 * d2 + d3 * d3;
        float4 o;                     // straight-through: z + (q - z), as reference
        o.x = zv.x + (qv.x - zv.x);
        o.y = zv.y + (qv.y - zv.y);
        o.z = zv.z + (qv.z - zv.z);
        o.w = zv.w + (qv.w - zv.w);
        qo[i] = o;
        red_v4(dwr + 4 * i, zv);
    }
    if (!half) {
        out[IDX_OFF + token] = (float)besti;
        atomicAdd(&g_counts[besti], 1.0f);
    }
    #pragma unroll
    for (int off = 16; off; off >>= 1) loss += __shfl_xor_sync(FULL, loss, off);
    if (lane == 0) atomicAdd(&g_loss, loss);
}

// ---------------- kernel 3: new_cluster_size, n, loss scalar ----------------
__global__ void vq_stats(const float* __restrict__ cluster_size,
                         float* __restrict__ out) {
    __shared__ float s[NUM_CODES];
    const int k = threadIdx.x;
    const float ncs = DECAY * cluster_size[k] + OMD * g_counts[k];
    out[CS_OFF + k] = ncs;
    s[k] = ncs;
    __syncthreads();
    for (int o = NUM_CODES / 2; o > 0; o >>= 1) {
        if (k < o) s[k] += s[k + o];
        __syncthreads();
    }
    if (k == 0) {
        g_n = s[0];
        out[LOSS_OFF] = g_loss / (float)(N_TOKENS * CODE_DIM);
    }
}

// ---------------- kernel 4: new_ema_w + new_codebook ----------------
__global__ void vq_finalize(const float* __restrict__ cluster_size,
                            const float* __restrict__ ema_w,
                            float* __restrict__ out) {
    const int i = blockIdx.x * blockDim.x + threadIdx.x;
    const int k = i >> 6;
    const float n     = g_n;
    const float ncs   = DECAY * cluster_size[k] + OMD * g_counts[k];
    const float denom = (ncs + EPS_F) / (n + (float)NUM_CODES * EPS_F) * n;
    const float nw    = DECAY * ema_w[i] + OMD * g_dw[i];
    out[EMA_OFF + i] = nw;
    out[CB_OFF + i]  = nw / denom;
}

// ---------------- launch ----------------
extern "C" void kernel_launch(void* const* d_in, const int* in_sizes, int n_in,
                              void* d_out, int out_size) {
    const float* z            = (const float*)d_in[0];
    const float* codebook     = (const float*)d_in[1];
    const float* cluster_size = (const float*)d_in[2];
    const float* ema_w        = (const float*)d_in[3];
    float* out = (float*)d_out;

    vq_zero<<<(NUM_CODES * CODE_DIM + 256) / 256 + 1, 256>>>();
    vq_prep_cb<<<(N_NTILES * 32) / 256, 256>>>(codebook);
    vq_main<<<N_MTILES / 8, 256>>>(z, codebook, out);
    vq_stats<<<1, NUM_CODES>>>(cluster_size, out);
    vq_finalize<<<NUM_CODES * CODE_DIM / 256, 256>>>(cluster_size, ema_w, out);
}